// round 1
// baseline (speedup 1.0000x reference)
#include <cuda_runtime.h>

// ---------------------------------------------------------------------------
// Spconv (9-tap rulebook) + LeakyReLU + BatchNorm1d (training stats), fp32.
//   out = BN(LeakyReLU(sum_k gather(features, idx[k]) * mask[k] @ W[k]))
// N = in_sizes[0]/32, C_in = C_out = 32, K = 9.
// ---------------------------------------------------------------------------

#define FULLMASK 0xffffffffu
#define NEG_SLOPE 0.01f
#define BN_EPS 1e-5f

__device__ int    g_mask_mode;     // 0 = float32, 1 = int32, 2 = uint8/bool
__device__ double g_sum[32];
__device__ double g_sumsq[32];
__device__ float  g_scale[32];
__device__ float  g_bias[32];

// packed f32x2 FMA (2 independent fp32 FMAs per issue slot; ptxas won't emit
// FFMA2 from plain C++ — PTX only)
__device__ __forceinline__ unsigned long long fma2(unsigned long long a,
                                                   unsigned long long b,
                                                   unsigned long long c) {
    unsigned long long d;
    asm("fma.rn.f32x2 %0, %1, %2, %3;" : "=l"(d) : "l"(a), "l"(b), "l"(c));
    return d;
}

__device__ __forceinline__ unsigned long long pack2(float f) {
    unsigned long long r;
    unsigned u = __float_as_uint(f);
    asm("mov.b64 %0, {%1, %1};" : "=l"(r) : "r"(u));
    return r;
}

// ---------------------------------------------------------------------------
// K0: zero BN accumulators + detect mask dtype.
//  - any word == 0x3F800000  -> float32 (bool bytes 0/1 and int 0/1 can't)
//  - else any word with bits in [8:32) -> uint8 bools (int32 0/1 can't)
//  - else int32
// ---------------------------------------------------------------------------
__global__ void k_init(const unsigned int* __restrict__ mask_words) {
    __shared__ int s_f32, s_u8;
    int t = threadIdx.x;
    if (t == 0) { s_f32 = 0; s_u8 = 0; }
    if (t < 32) { g_sum[t] = 0.0; g_sumsq[t] = 0.0; }
    __syncthreads();
    int f32 = 0, u8 = 0;
#pragma unroll
    for (int i = 0; i < 4; i++) {
        unsigned w = mask_words[t * 4 + i];   // 64 threads * 4 = 256 words (1KB, safe)
        if (w == 0x3F800000u) f32 = 1;
        else if (w & 0xFFFFFF00u) u8 = 1;
    }
    if (f32) atomicOr(&s_f32, 1);
    if (u8)  atomicOr(&s_u8, 1);
    __syncthreads();
    if (t == 0) g_mask_mode = s_f32 ? 0 : (s_u8 ? 2 : 1);
}

// ---------------------------------------------------------------------------
// K1: gather -> 9x [32x32] GEMM -> LeakyReLU -> write y, accumulate BN stats.
// One thread per voxel. 16 f32x2 accumulators = 32 output channels.
// W staged in shared (36 KB), read as 16B broadcasts (conflict-free).
// ---------------------------------------------------------------------------
__global__ void __launch_bounds__(128) k_conv(
    const float* __restrict__ feat,     // [N,32]
    const float* __restrict__ weight,   // [9,32,32]
    const int*   __restrict__ nidx,     // [9,N]
    const void*  __restrict__ nmask,    // [9,N] dtype per g_mask_mode
    float* __restrict__ out,            // [N,32]  (pre-BN y)
    int N)
{
    __shared__ float Ws[9 * 32 * 32];
    for (int i = threadIdx.x; i < 9 * 32 * 32 / 4; i += blockDim.x)
        ((float4*)Ws)[i] = ((const float4*)weight)[i];
    __syncthreads();

    const int n = blockIdx.x * blockDim.x + threadIdx.x;
    const int mode = g_mask_mode;
    const int lane = threadIdx.x & 31;

    unsigned long long acc[16];
#pragma unroll
    for (int j = 0; j < 16; j++) acc[j] = 0ull;   // (0.f, 0.f)

    if (n < N) {
        for (int k = 0; k < 9; k++) {
            const size_t ofs = (size_t)k * (size_t)N + (size_t)n;
            float m;
            if (mode == 0)      m = ((const float*)nmask)[ofs];
            else if (mode == 1) m = (float)((const int*)nmask)[ofs];
            else                m = (float)((const unsigned char*)nmask)[ofs];

            float f[32];
            if (m != 0.0f) {
                const int j = nidx[ofs];
                const float4* fr = (const float4*)(feat + (size_t)j * 32);
#pragma unroll
                for (int q = 0; q < 8; q++) {
                    float4 v = fr[q];
                    f[4 * q + 0] = v.x * m;
                    f[4 * q + 1] = v.y * m;
                    f[4 * q + 2] = v.z * m;
                    f[4 * q + 3] = v.w * m;
                }
            } else {
#pragma unroll
                for (int q = 0; q < 32; q++) f[q] = 0.0f;
            }

            const float* Wk = Ws + k * 1024;
#pragma unroll
            for (int ci = 0; ci < 32; ci++) {
                const unsigned long long a2 = pack2(f[ci]);
                const ulonglong2* wrow = (const ulonglong2*)(Wk + ci * 32);
#pragma unroll
                for (int q = 0; q < 8; q++) {
                    ulonglong2 wv = wrow[q];           // LDS.128 broadcast
                    acc[2 * q + 0] = fma2(a2, wv.x, acc[2 * q + 0]);
                    acc[2 * q + 1] = fma2(a2, wv.y, acc[2 * q + 1]);
                }
            }
        }
    }

    // unpack, LeakyReLU
    float y[32];
#pragma unroll
    for (int q = 0; q < 8; q++) {
#pragma unroll
        for (int h = 0; h < 2; h++) {
            unsigned long long a = acc[2 * q + h];
            float lo = __uint_as_float((unsigned)(a & 0xffffffffull));
            float hi = __uint_as_float((unsigned)(a >> 32));
            y[4 * q + 2 * h + 0] = (lo >= 0.0f) ? lo : NEG_SLOPE * lo;
            y[4 * q + 2 * h + 1] = (hi >= 0.0f) ? hi : NEG_SLOPE * hi;
        }
    }

    if (n < N) {
        float4* orow = (float4*)(out + (size_t)n * 32);
#pragma unroll
        for (int q = 0; q < 8; q++)
            orow[q] = make_float4(y[4 * q], y[4 * q + 1], y[4 * q + 2], y[4 * q + 3]);
    }

    // per-warp channel reduction (xor butterfly), then double atomics.
    float z[32];
#pragma unroll
    for (int c = 0; c < 32; c++) z[c] = y[c] * y[c];
#pragma unroll
    for (int off = 16; off > 0; off >>= 1) {
#pragma unroll
        for (int c = 0; c < 32; c++) {
            y[c] += __shfl_xor_sync(FULLMASK, y[c], off);
            z[c] += __shfl_xor_sync(FULLMASK, z[c], off);
        }
    }
    // lane l commits channel l (static index via predication)
#pragma unroll
    for (int c = 0; c < 32; c++) {
        if (lane == c) {
            atomicAdd(&g_sum[c],   (double)y[c]);
            atomicAdd(&g_sumsq[c], (double)z[c]);
        }
    }
}

// ---------------------------------------------------------------------------
// K2: finalize BN affine parameters.
// ---------------------------------------------------------------------------
__global__ void k_bn(const float* __restrict__ gamma,
                     const float* __restrict__ beta, int N) {
    int t = threadIdx.x;
    if (t < 32) {
        double invN = 1.0 / (double)N;
        double mean = g_sum[t] * invN;
        double var  = g_sumsq[t] * invN - mean * mean;
        float sc = gamma[t] * rsqrtf((float)var + BN_EPS);
        g_scale[t] = sc;
        g_bias[t]  = beta[t] - (float)mean * sc;
    }
}

// ---------------------------------------------------------------------------
// K3: in-place normalize, float4 vectorized.
// ---------------------------------------------------------------------------
__global__ void k_norm(float* __restrict__ out, long long total4) {
    long long i = (long long)blockIdx.x * blockDim.x + threadIdx.x;
    if (i >= total4) return;
    int cb = ((int)i & 7) * 4;     // base channel of this float4
    float4 v = ((float4*)out)[i];
    v.x = v.x * g_scale[cb + 0] + g_bias[cb + 0];
    v.y = v.y * g_scale[cb + 1] + g_bias[cb + 1];
    v.z = v.z * g_scale[cb + 2] + g_bias[cb + 2];
    v.w = v.w * g_scale[cb + 3] + g_bias[cb + 3];
    ((float4*)out)[i] = v;
}

// ---------------------------------------------------------------------------
extern "C" void kernel_launch(void* const* d_in, const int* in_sizes, int n_in,
                              void* d_out, int out_size) {
    const float* feat  = (const float*)d_in[0];   // [N,32]
    const float* wt    = (const float*)d_in[1];   // [9,32,32]
    const float* gamma = (const float*)d_in[2];   // [32]
    const float* beta  = (const float*)d_in[3];   // [32]
    const int*   nidx  = (const int*)d_in[4];     // [9,N]
    const void*  nmask = d_in[5];                 // [9,N]
    float* out = (float*)d_out;

    const int N = in_sizes[0] / 32;

    k_init<<<1, 64>>>((const unsigned int*)nmask);

    const int blocks = (N + 127) / 128;
    k_conv<<<blocks, 128>>>(feat, wt, nidx, nmask, out, N);

    k_bn<<<1, 32>>>(gamma, beta, N);

    const long long total4 = (long long)N * 8;
    const int nblocks = (int)((total4 + 255) / 256);
    k_norm<<<nblocks, 256>>>(out, total4);
}

// round 2
// speedup vs baseline: 1.4249x; 1.4249x over previous
#include <cuda_runtime.h>

// ---------------------------------------------------------------------------
// Spconv (9-tap rulebook) + LeakyReLU + BatchNorm1d (training stats), fp32.
// Round 2: 2-voxel register blocking (halves weight-LDS per voxel),
// streamed float4 feature chunks, block-level BN-stat reduction.
// ---------------------------------------------------------------------------

#define FULLMASK 0xffffffffu
#define NEG_SLOPE 0.01f
#define BN_EPS 1e-5f

__device__ int    g_mask_mode;     // 0 = float32, 1 = int32, 2 = uint8/bool
__device__ double g_sum[32];
__device__ double g_sumsq[32];
__device__ float  g_scale[32];
__device__ float  g_bias[32];

// packed f32x2 FMA (2 independent fp32 FMAs per issue; PTX-only form)
__device__ __forceinline__ unsigned long long fma2(unsigned long long a,
                                                   unsigned long long b,
                                                   unsigned long long c) {
    unsigned long long d;
    asm("fma.rn.f32x2 %0, %1, %2, %3;" : "=l"(d) : "l"(a), "l"(b), "l"(c));
    return d;
}

__device__ __forceinline__ unsigned long long pack2(float f) {
    unsigned long long r;
    unsigned u = __float_as_uint(f);
    asm("mov.b64 %0, {%1, %1};" : "=l"(r) : "r"(u));
    return r;
}

// ---------------------------------------------------------------------------
// K0: zero BN accumulators + detect mask dtype.
// ---------------------------------------------------------------------------
__global__ void k_init(const unsigned int* __restrict__ mask_words) {
    __shared__ int s_f32, s_u8;
    int t = threadIdx.x;
    if (t == 0) { s_f32 = 0; s_u8 = 0; }
    if (t < 32) { g_sum[t] = 0.0; g_sumsq[t] = 0.0; }
    __syncthreads();
    int f32 = 0, u8 = 0;
#pragma unroll
    for (int i = 0; i < 4; i++) {
        unsigned w = mask_words[t * 4 + i];
        if (w == 0x3F800000u) f32 = 1;
        else if (w & 0xFFFFFF00u) u8 = 1;
    }
    if (f32) atomicOr(&s_f32, 1);
    if (u8)  atomicOr(&s_u8, 1);
    __syncthreads();
    if (t == 0) g_mask_mode = s_f32 ? 0 : (s_u8 ? 2 : 1);
}

// ---------------------------------------------------------------------------
// K1: gather -> 9x [32x32] GEMM -> LeakyReLU -> y, + BN stats.
// 128 threads/block, 2 voxels/thread (n0 = base+t, n1 = base+t+128).
// Weights in shared; each LDS.128 weight read feeds FMAs for BOTH voxels.
// ---------------------------------------------------------------------------
__global__ void __launch_bounds__(128, 3) k_conv(
    const float* __restrict__ feat,     // [N,32]
    const float* __restrict__ weight,   // [9,32,32]
    const int*   __restrict__ nidx,     // [9,N]
    const void*  __restrict__ nmask,    // [9,N]
    float* __restrict__ out,            // [N,32]  (pre-BN y)
    int N)
{
    __shared__ float  Ws[9 * 32 * 32];
    __shared__ double s_sum[32];
    __shared__ double s_sumsq[32];

    const int t = threadIdx.x;
    for (int i = t; i < 9 * 32 * 32 / 4; i += blockDim.x)
        ((float4*)Ws)[i] = ((const float4*)weight)[i];
    if (t < 32) { s_sum[t] = 0.0; s_sumsq[t] = 0.0; }
    __syncthreads();

    const int base = blockIdx.x * 256;
    const int n0 = base + t;
    const int n1 = base + t + 128;
    const bool v0ok = (n0 < N);
    const bool v1ok = (n1 < N);
    const int mode = g_mask_mode;
    const int lane = t & 31;

    unsigned long long acc0[16], acc1[16];
#pragma unroll
    for (int j = 0; j < 16; j++) { acc0[j] = 0ull; acc1[j] = 0ull; }

    for (int k = 0; k < 9; k++) {
        const size_t kb = (size_t)k * (size_t)N;
        float m0 = 0.0f, m1 = 0.0f;
        if (mode == 0) {
            const float* mp = (const float*)nmask;
            if (v0ok) m0 = mp[kb + n0];
            if (v1ok) m1 = mp[kb + n1];
        } else if (mode == 1) {
            const int* mp = (const int*)nmask;
            if (v0ok) m0 = (float)mp[kb + n0];
            if (v1ok) m1 = (float)mp[kb + n1];
        } else {
            const unsigned char* mp = (const unsigned char*)nmask;
            if (v0ok) m0 = (float)mp[kb + n0];
            if (v1ok) m1 = (float)mp[kb + n1];
        }
        int j0 = 0, j1 = 0;
        if (m0 != 0.0f) j0 = nidx[kb + n0];
        if (m1 != 0.0f) j1 = nidx[kb + n1];
        const float4* p0 = (const float4*)(feat + (size_t)j0 * 32);
        const float4* p1 = (const float4*)(feat + (size_t)j1 * 32);
        const ulonglong2* wk = (const ulonglong2*)(Ws + k * 1024);

#pragma unroll
        for (int c = 0; c < 8; c++) {
            float4 v0 = make_float4(0.f, 0.f, 0.f, 0.f);
            float4 v1 = make_float4(0.f, 0.f, 0.f, 0.f);
            if (m0 != 0.0f) {
                float4 r = p0[c];
                v0 = make_float4(r.x * m0, r.y * m0, r.z * m0, r.w * m0);
            }
            if (m1 != 0.0f) {
                float4 r = p1[c];
                v1 = make_float4(r.x * m1, r.y * m1, r.z * m1, r.w * m1);
            }
            const float fv0[4] = {v0.x, v0.y, v0.z, v0.w};
            const float fv1[4] = {v1.x, v1.y, v1.z, v1.w};
#pragma unroll
            for (int i = 0; i < 4; i++) {
                const unsigned long long a0 = pack2(fv0[i]);
                const unsigned long long a1 = pack2(fv1[i]);
                const ulonglong2* wr = wk + (c * 4 + i) * 8;
#pragma unroll
                for (int q = 0; q < 8; q++) {
                    const ulonglong2 wv = wr[q];       // LDS.128 broadcast, shared by both voxels
                    acc0[2 * q + 0] = fma2(a0, wv.x, acc0[2 * q + 0]);
                    acc0[2 * q + 1] = fma2(a0, wv.y, acc0[2 * q + 1]);
                    acc1[2 * q + 0] = fma2(a1, wv.x, acc1[2 * q + 0]);
                    acc1[2 * q + 1] = fma2(a1, wv.y, acc1[2 * q + 1]);
                }
            }
        }
    }

    // unpack + LeakyReLU
    float y0[32], y1[32];
#pragma unroll
    for (int q = 0; q < 16; q++) {
        {
            unsigned long long a = acc0[q];
            float lo = __uint_as_float((unsigned)(a & 0xffffffffull));
            float hi = __uint_as_float((unsigned)(a >> 32));
            y0[2 * q + 0] = (lo >= 0.0f) ? lo : NEG_SLOPE * lo;
            y0[2 * q + 1] = (hi >= 0.0f) ? hi : NEG_SLOPE * hi;
        }
        {
            unsigned long long a = acc1[q];
            float lo = __uint_as_float((unsigned)(a & 0xffffffffull));
            float hi = __uint_as_float((unsigned)(a >> 32));
            y1[2 * q + 0] = (lo >= 0.0f) ? lo : NEG_SLOPE * lo;
            y1[2 * q + 1] = (hi >= 0.0f) ? hi : NEG_SLOPE * hi;
        }
    }

    if (v0ok) {
        float4* orow = (float4*)(out + (size_t)n0 * 32);
#pragma unroll
        for (int q = 0; q < 8; q++)
            orow[q] = make_float4(y0[4 * q], y0[4 * q + 1], y0[4 * q + 2], y0[4 * q + 3]);
    }
    if (v1ok) {
        float4* orow = (float4*)(out + (size_t)n1 * 32);
#pragma unroll
        for (int q = 0; q < 8; q++)
            orow[q] = make_float4(y1[4 * q], y1[4 * q + 1], y1[4 * q + 2], y1[4 * q + 3]);
    }

    // BN stats: combine both voxels, warp butterfly, block smem reduce.
    float s[32], z[32];
#pragma unroll
    for (int c = 0; c < 32; c++) {
        float a = v0ok ? y0[c] : 0.0f;
        float b = v1ok ? y1[c] : 0.0f;
        s[c] = a + b;
        z[c] = a * a + b * b;
    }
#pragma unroll
    for (int off = 16; off > 0; off >>= 1) {
#pragma unroll
        for (int c = 0; c < 32; c++) {
            s[c] += __shfl_xor_sync(FULLMASK, s[c], off);
            z[c] += __shfl_xor_sync(FULLMASK, z[c], off);
        }
    }
#pragma unroll
    for (int c = 0; c < 32; c++) {
        if (lane == c) {
            atomicAdd(&s_sum[c],   (double)s[c]);
            atomicAdd(&s_sumsq[c], (double)z[c]);
        }
    }
    __syncthreads();
    if (t < 32) {
        atomicAdd(&g_sum[t],   s_sum[t]);
        atomicAdd(&g_sumsq[t], s_sumsq[t]);
    }
}

// ---------------------------------------------------------------------------
// K2: finalize BN affine parameters.
// ---------------------------------------------------------------------------
__global__ void k_bn(const float* __restrict__ gamma,
                     const float* __restrict__ beta, int N) {
    int t = threadIdx.x;
    if (t < 32) {
        double invN = 1.0 / (double)N;
        double mean = g_sum[t] * invN;
        double var  = g_sumsq[t] * invN - mean * mean;
        float sc = gamma[t] * rsqrtf((float)var + BN_EPS);
        g_scale[t] = sc;
        g_bias[t]  = beta[t] - (float)mean * sc;
    }
}

// ---------------------------------------------------------------------------
// K3: in-place normalize, float4 vectorized.
// ---------------------------------------------------------------------------
__global__ void k_norm(float* __restrict__ out, long long total4) {
    long long i = (long long)blockIdx.x * blockDim.x + threadIdx.x;
    if (i >= total4) return;
    int cb = ((int)i & 7) * 4;
    float4 v = ((float4*)out)[i];
    v.x = v.x * g_scale[cb + 0] + g_bias[cb + 0];
    v.y = v.y * g_scale[cb + 1] + g_bias[cb + 1];
    v.z = v.z * g_scale[cb + 2] + g_bias[cb + 2];
    v.w = v.w * g_scale[cb + 3] + g_bias[cb + 3];
    ((float4*)out)[i] = v;
}

// ---------------------------------------------------------------------------
extern "C" void kernel_launch(void* const* d_in, const int* in_sizes, int n_in,
                              void* d_out, int out_size) {
    const float* feat  = (const float*)d_in[0];
    const float* wt    = (const float*)d_in[1];
    const float* gamma = (const float*)d_in[2];
    const float* beta  = (const float*)d_in[3];
    const int*   nidx  = (const int*)d_in[4];
    const void*  nmask = d_in[5];
    float* out = (float*)d_out;

    const int N = in_sizes[0] / 32;

    k_init<<<1, 64>>>((const unsigned int*)nmask);

    const int blocks = (N + 255) / 256;
    k_conv<<<blocks, 128>>>(feat, wt, nidx, nmask, out, N);

    k_bn<<<1, 32>>>(gamma, beta, N);

    const long long total4 = (long long)N * 8;
    const int nblocks = (int)((total4 + 255) / 256);
    k_norm<<<nblocks, 256>>>(out, total4);
}